// round 15
// baseline (speedup 1.0000x reference)
#include <cuda_runtime.h>
#include <math.h>
#include <stdint.h>

// Problem-fixed sizes: N=100000, E=3200000, NF=16, H=32, HO=64
#define NMAX 100000
#define NF 16
#define H  32
#define HO 64
#define NBANK 8

__device__ float  g_agg[NMAX * NF];
__device__ float  g_h1 [NMAX * H];
__device__ float  g_h2 [NMAX * H];
__device__ double g_s1 [NBANK * 64];   // per-bank: sum[32], sumsq[32]
__device__ double g_s2 [NBANK * 64];
__device__ int    g_is64;

__device__ __forceinline__ float gelu_exact(float v) {
    return 0.5f * v * (1.0f + erff(v * 0.70710678118654752f));
}

// ---------------------------------------------------------------------------
// K0: zero g_agg + banked stats; detect edge_index dtype
// ---------------------------------------------------------------------------
__global__ __launch_bounds__(256) void k_pre(const int* __restrict__ eidx32,
                                             int n4) {
    int i = blockIdx.x * blockDim.x + threadIdx.x;
    if (i < n4) ((float4*)g_agg)[i] = make_float4(0.f, 0.f, 0.f, 0.f);
    if (blockIdx.x == 0) {
        #pragma unroll
        for (int k = 0; k < NBANK * 64 / 256; k++) {
            g_s1[threadIdx.x + k * 256] = 0.0;
            g_s2[threadIdx.x + k * 256] = 0.0;
        }
        if (threadIdx.x == 0) {
            int nz = 0;
            #pragma unroll
            for (int k = 0; k < 64; k++) nz |= eidx32[2 * k + 1];
            g_is64 = (nz == 0) ? 1 : 0;
        }
    }
}

// ---------------------------------------------------------------------------
// K1: edge kernel (R9 — proven): 4 threads/edge, grid-stride, index prefetch,
// weights in registers, __ldcs streaming for idx/ea.
// ---------------------------------------------------------------------------
__global__ __launch_bounds__(256) void k_edge(const float* __restrict__ x,
                                              const void*  __restrict__ eidx,
                                              const float* __restrict__ ea,
                                              const float* __restrict__ We,
                                              const float* __restrict__ be,
                                              int E) {
    int t = blockIdx.x * blockDim.x + threadIdx.x;
    int c = t & 3;

    float w[8][4];
    #pragma unroll
    for (int k = 0; k < 8; k++) {
        float4 wv = __ldg((const float4*)(We + k * 16) + c);
        w[k][0] = wv.x; w[k][1] = wv.y; w[k][2] = wv.z; w[k][3] = wv.w;
    }
    float4 bv = __ldg(((const float4*)be) + c);
    int is64 = g_is64;

    int total  = E * 4;
    int stride = gridDim.x * blockDim.x;
    const int*       p32 = (const int*)eidx;
    const long long* p64 = (const long long*)eidx;

    int gt = t;
    if (gt >= total) return;

    int src, dst;
    {
        int e = gt >> 2;
        if (is64) { src = (int)__ldcs(p64 + e); dst = (int)__ldcs(p64 + e + E); }
        else      { src = __ldcs(p32 + e);      dst = __ldcs(p32 + e + E);      }
    }

    while (gt < total) {
        int gtn = gt + stride;
        int srcN = 0, dstN = 0;
        if (gtn < total) {
            int en = gtn >> 2;
            if (is64) { srcN = (int)__ldcs(p64 + en); dstN = (int)__ldcs(p64 + en + E); }
            else      { srcN = __ldcs(p32 + en);      dstN = __ldcs(p32 + en + E);      }
        }

        int e = gt >> 2;
        float4 xv = __ldg((const float4*)(x + (size_t)src * 16) + c);
        const float4* ear = (const float4*)(ea + (size_t)e * 8);
        float4 a0 = __ldcs(ear);
        float4 a1 = __ldcs(ear + 1);
        float av[8] = {a0.x, a0.y, a0.z, a0.w, a1.x, a1.y, a1.z, a1.w};

        float m0 = bv.x, m1 = bv.y, m2 = bv.z, m3 = bv.w;
        #pragma unroll
        for (int k = 0; k < 8; k++) {
            m0 = fmaf(av[k], w[k][0], m0);
            m1 = fmaf(av[k], w[k][1], m1);
            m2 = fmaf(av[k], w[k][2], m2);
            m3 = fmaf(av[k], w[k][3], m3);
        }

        float4 r;
        r.x = fmaxf(xv.x + m0, 0.0f);
        r.y = fmaxf(xv.y + m1, 0.0f);
        r.z = fmaxf(xv.z + m2, 0.0f);
        r.w = fmaxf(xv.w + m3, 0.0f);
        atomicAdd((float4*)(g_agg + (size_t)dst * 16) + c, r);

        gt = gtn; src = srcN; dst = dstN;
    }
}

// ---------------------------------------------------------------------------
// stats epilogue, acc[16] per thread (2 thr/node layout):
// lane L holds features [(L&1)*16,+16) of node (L>>1); stride-2 reduce.
// ---------------------------------------------------------------------------
__device__ __forceinline__ void stats_epilogue16(const float* acc, bool valid,
                                                 double* sums) {
    __shared__ float tr[8][16][33];
    __shared__ float comb[8][32];
    int lane = threadIdx.x & 31;
    int wid  = threadIdx.x >> 5;
    int f    = lane & 15;
    bool isq = lane >= 16;
    int bank = blockIdx.x & (NBANK - 1);

    #pragma unroll
    for (int j = 0; j < 16; j++)
        tr[wid][j][lane] = valid ? acc[j] : 0.0f;
    __syncwarp();

    float red[2];
    #pragma unroll
    for (int h = 0; h < 2; h++) {
        float r = 0.0f;
        #pragma unroll
        for (int k = 0; k < 16; k++) {
            float v = tr[wid][f][2 * k + h];
            r = fmaf(v, isq ? v : 1.0f, r);
        }
        red[h] = r;
    }

    #pragma unroll
    for (int h = 0; h < 2; h++) {
        comb[wid][lane] = red[h];
        __syncthreads();
        if (wid == 0) {
            float ts = 0.0f;
            #pragma unroll
            for (int w = 0; w < 8; w++) ts += comb[w][lane];
            atomicAdd(&sums[bank * 64 + (isq ? 32 : 0) + h * 16 + f],
                      (double)ts);
        }
        __syncthreads();
    }
}

// ---------------------------------------------------------------------------
// BN finalize inline: sum the 8 banks, then scale/shift
// ---------------------------------------------------------------------------
__device__ __forceinline__ void fin_inline(const double* __restrict__ sums,
                                           const float* __restrict__ gamma,
                                           const float* __restrict__ beta,
                                           int N, float* ssc, float* ssh) {
    if (threadIdx.x < H) {
        int f = threadIdx.x;
        double s = 0.0, q = 0.0;
        #pragma unroll
        for (int b = 0; b < NBANK; b++) {
            s += sums[b * 64 + f];
            q += sums[b * 64 + 32 + f];
        }
        double mean = s / (double)N;
        double var  = q / (double)N - mean * mean;
        double inv  = 1.0 / sqrt(var + 1e-5);
        ssc[f] = (float)((double)gamma[f] * inv);
        ssh[f] = (float)((double)beta[f] - mean * (double)gamma[f] * inv);
    }
}

// ---------------------------------------------------------------------------
// K2: h1 = ((1+eps)*x + agg) @ W1 + b1.  R12 form (proven 14.7us).
// ---------------------------------------------------------------------------
__global__ __launch_bounds__(256) void k_gemm1(const float* __restrict__ x,
                                               const float* __restrict__ epsp,
                                               const float* __restrict__ W1,
                                               const float* __restrict__ b1,
                                               int N) {
    __shared__ float sW[NF * H];
    __shared__ float sb[H];
    for (int i = threadIdx.x; i < NF * H; i += blockDim.x) sW[i] = W1[i];
    if (threadIdx.x < H) sb[threadIdx.x] = b1[threadIdx.x];
    __syncthreads();

    int t = blockIdx.x * blockDim.x + threadIdx.x;
    int n = t >> 1, half = t & 1;
    bool valid = n < N;
    int nc = valid ? n : 0;
    float sc = 1.0f + epsp[0];

    const float4* ar = (const float4*)(g_agg + (size_t)nc * NF);
    const float4* xr = (const float4*)(x     + (size_t)nc * NF);
    int hoff = half * 16;

    float acc[16];
    #pragma unroll
    for (int j = 0; j < 16; j++) acc[j] = sb[hoff + j];

    #pragma unroll 1
    for (int cph = 0; cph < 4; cph++) {
        float4 v  = ar[cph];
        float4 xv = xr[cph];
        float a0 = fmaf(sc, xv.x, v.x);
        float a1 = fmaf(sc, xv.y, v.y);
        float a2 = fmaf(sc, xv.z, v.z);
        float a3 = fmaf(sc, xv.w, v.w);
        const float* w0 = sW + (4 * cph + 0) * H + hoff;
        const float* w1 = sW + (4 * cph + 1) * H + hoff;
        const float* w2 = sW + (4 * cph + 2) * H + hoff;
        const float* w3 = sW + (4 * cph + 3) * H + hoff;
        #pragma unroll
        for (int j = 0; j < 16; j++) {
            float t0 = fmaf(a0, w0[j], acc[j]);
            float t1 = fmaf(a1, w1[j], t0);
            float t2 = fmaf(a2, w2[j], t1);
            acc[j]   = fmaf(a3, w3[j], t2);
        }
    }

    if (valid) {
        float4* hr = (float4*)(g_h1 + (size_t)n * H + hoff);
        #pragma unroll
        for (int cph = 0; cph < 4; cph++)
            hr[cph] = make_float4(acc[4*cph], acc[4*cph+1], acc[4*cph+2], acc[4*cph+3]);
    }
    stats_epilogue16(acc, valid, g_s1);
}

// ---------------------------------------------------------------------------
// K3: h2 = gelu(bn1(h1)) @ W2 + b2.  2 thr/node OUTPUT split, gelu streamed
// and SHARED via shfl (compile-time indices only — no local arrays).
// Iter i: own 4 gelu (features 16*half+4i..), shuffle partner's 4,
// predicated-select into (lo=features 4i.., hi=features 16+4i..), FMA 8 rows.
// ---------------------------------------------------------------------------
__global__ __launch_bounds__(256) void k_gemm2(const float* __restrict__ g1,
                                               const float* __restrict__ bt1,
                                               const float* __restrict__ W2,
                                               const float* __restrict__ b2,
                                               int N) {
    __shared__ float sW[H * H];
    __shared__ float sb[H], ssc[H], ssh[H];
    for (int i = threadIdx.x; i < H * H; i += blockDim.x) sW[i] = W2[i];
    if (threadIdx.x < H) sb[threadIdx.x] = b2[threadIdx.x];
    fin_inline(g_s1, g1, bt1, N, ssc, ssh);
    __syncthreads();

    int t = blockIdx.x * blockDim.x + threadIdx.x;
    int n = t >> 1, half = t & 1;
    bool valid = n < N;
    int nc = valid ? n : 0;
    int koff = half * 16;     // own input chunk
    int hoff = half * 16;     // own output chunk

    const float4* hr = (const float4*)(g_h1 + (size_t)nc * H + koff);

    float acc[16];
    #pragma unroll
    for (int j = 0; j < 16; j++) acc[j] = sb[hoff + j];

    bool lowHalf = (half == 0);

    #pragma unroll 1
    for (int i = 0; i < 4; i++) {
        float4 v = hr[i];
        int fb = koff + 4 * i;
        float g0 = gelu_exact(fmaf(v.x, ssc[fb + 0], ssh[fb + 0]));
        float g1v = gelu_exact(fmaf(v.y, ssc[fb + 1], ssh[fb + 1]));
        float g2 = gelu_exact(fmaf(v.z, ssc[fb + 2], ssh[fb + 2]));
        float g3 = gelu_exact(fmaf(v.w, ssc[fb + 3], ssh[fb + 3]));

        float p0 = __shfl_xor_sync(0xffffffffu, g0, 1);
        float p1 = __shfl_xor_sync(0xffffffffu, g1v, 1);
        float p2 = __shfl_xor_sync(0xffffffffu, g2, 1);
        float p3 = __shfl_xor_sync(0xffffffffu, g3, 1);

        // lo = features 4i+r (global), hi = features 16+4i+r
        float l0 = lowHalf ? g0 : p0,  h0 = lowHalf ? p0 : g0;
        float l1 = lowHalf ? g1v : p1, h1 = lowHalf ? p1 : g1v;
        float l2 = lowHalf ? g2 : p2,  h2 = lowHalf ? p2 : g2;
        float l3 = lowHalf ? g3 : p3,  h3 = lowHalf ? p3 : g3;

        const float* wl0 = sW + (4 * i + 0) * H + hoff;
        const float* wl1 = sW + (4 * i + 1) * H + hoff;
        const float* wl2 = sW + (4 * i + 2) * H + hoff;
        const float* wl3 = sW + (4 * i + 3) * H + hoff;
        const float* wh0 = sW + (16 + 4 * i + 0) * H + hoff;
        const float* wh1 = sW + (16 + 4 * i + 1) * H + hoff;
        const float* wh2 = sW + (16 + 4 * i + 2) * H + hoff;
        const float* wh3 = sW + (16 + 4 * i + 3) * H + hoff;
        #pragma unroll
        for (int j = 0; j < 16; j++) {
            float a = acc[j];
            a = fmaf(l0, wl0[j], a);
            a = fmaf(l1, wl1[j], a);
            a = fmaf(l2, wl2[j], a);
            a = fmaf(l3, wl3[j], a);
            a = fmaf(h0, wh0[j], a);
            a = fmaf(h1, wh1[j], a);
            a = fmaf(h2, wh2[j], a);
            a = fmaf(h3, wh3[j], a);
            acc[j] = a;
        }
    }

    if (valid) {
        float4* o = (float4*)(g_h2 + (size_t)n * H + hoff);
        #pragma unroll
        for (int cph = 0; cph < 4; cph++)
            o[cph] = make_float4(acc[4*cph], acc[4*cph+1], acc[4*cph+2], acc[4*cph+3]);
    }
    stats_epilogue16(acc, valid, g_s2);
}

// ---------------------------------------------------------------------------
// K4: out = gelu(bn2(h2)) @ W3 + b3.  Same streamed shared-gelu pattern,
// 2 thr/node, output split (32 outputs each), acc[32].
// ---------------------------------------------------------------------------
__global__ __launch_bounds__(256) void k_out(const float* __restrict__ g2,
                                             const float* __restrict__ bt2,
                                             const float* __restrict__ W3,
                                             const float* __restrict__ b3,
                                             float* __restrict__ out,
                                             int N) {
    __shared__ float sW[H * HO];
    __shared__ float sb[HO], ssc[H], ssh[H];
    for (int i = threadIdx.x; i < H * HO; i += blockDim.x) sW[i] = W3[i];
    if (threadIdx.x < HO) sb[threadIdx.x] = b3[threadIdx.x];
    fin_inline(g_s2, g2, bt2, N, ssc, ssh);
    __syncthreads();

    int t = blockIdx.x * blockDim.x + threadIdx.x;
    int n = t >> 1, half = t & 1;
    bool valid = n < N;
    int nc = valid ? n : 0;
    int koff = half * 16;     // own input chunk
    int ooff = half * 32;     // own output chunk

    const float4* hr = (const float4*)(g_h2 + (size_t)nc * H + koff);

    float acc[32];
    #pragma unroll
    for (int j = 0; j < 32; j++) acc[j] = sb[ooff + j];

    bool lowHalf = (half == 0);

    #pragma unroll 1
    for (int i = 0; i < 4; i++) {
        float4 v = hr[i];
        int fb = koff + 4 * i;
        float g0 = gelu_exact(fmaf(v.x, ssc[fb + 0], ssh[fb + 0]));
        float g1v = gelu_exact(fmaf(v.y, ssc[fb + 1], ssh[fb + 1]));
        float g2 = gelu_exact(fmaf(v.z, ssc[fb + 2], ssh[fb + 2]));
        float g3 = gelu_exact(fmaf(v.w, ssc[fb + 3], ssh[fb + 3]));

        float p0 = __shfl_xor_sync(0xffffffffu, g0, 1);
        float p1 = __shfl_xor_sync(0xffffffffu, g1v, 1);
        float p2 = __shfl_xor_sync(0xffffffffu, g2, 1);
        float p3 = __shfl_xor_sync(0xffffffffu, g3, 1);

        float l0 = lowHalf ? g0 : p0,  h0 = lowHalf ? p0 : g0;
        float l1 = lowHalf ? g1v : p1, h1 = lowHalf ? p1 : g1v;
        float l2 = lowHalf ? g2 : p2,  h2 = lowHalf ? p2 : g2;
        float l3 = lowHalf ? g3 : p3,  h3 = lowHalf ? p3 : g3;

        const float* wl0 = sW + (4 * i + 0) * HO + ooff;
        const float* wl1 = sW + (4 * i + 1) * HO + ooff;
        const float* wl2 = sW + (4 * i + 2) * HO + ooff;
        const float* wl3 = sW + (4 * i + 3) * HO + ooff;
        const float* wh0 = sW + (16 + 4 * i + 0) * HO + ooff;
        const float* wh1 = sW + (16 + 4 * i + 1) * HO + ooff;
        const float* wh2 = sW + (16 + 4 * i + 2) * HO + ooff;
        const float* wh3 = sW + (16 + 4 * i + 3) * HO + ooff;
        #pragma unroll
        for (int j = 0; j < 32; j++) {
            float a = acc[j];
            a = fmaf(l0, wl0[j], a);
            a = fmaf(l1, wl1[j], a);
            a = fmaf(l2, wl2[j], a);
            a = fmaf(l3, wl3[j], a);
            a = fmaf(h0, wh0[j], a);
            a = fmaf(h1, wh1[j], a);
            a = fmaf(h2, wh2[j], a);
            a = fmaf(h3, wh3[j], a);
            acc[j] = a;
        }
    }

    if (valid) {
        float4* orow = (float4*)(out + (size_t)n * HO + ooff);
        #pragma unroll
        for (int cph = 0; cph < 8; cph++)
            orow[cph] = make_float4(acc[4*cph], acc[4*cph+1],
                                    acc[4*cph+2], acc[4*cph+3]);
    }
}

// ---------------------------------------------------------------------------
extern "C" void kernel_launch(void* const* d_in, const int* in_sizes, int n_in,
                              void* d_out, int out_size) {
    const float* x    = (const float*)d_in[0];
    const void*  eidx =               d_in[1];
    const float* ea   = (const float*)d_in[2];
    const float* We   = (const float*)d_in[3];
    const float* be   = (const float*)d_in[4];
    const float* W1   = (const float*)d_in[5];
    const float* b1   = (const float*)d_in[6];
    const float* g1   = (const float*)d_in[7];
    const float* bt1  = (const float*)d_in[8];
    const float* W2   = (const float*)d_in[9];
    const float* b2   = (const float*)d_in[10];
    const float* epsp = (const float*)d_in[11];
    const float* g2   = (const float*)d_in[12];
    const float* bt2  = (const float*)d_in[13];
    const float* W3   = (const float*)d_in[14];
    const float* b3   = (const float*)d_in[15];
    float* out = (float*)d_out;

    int N = in_sizes[0] / NF;
    int E = in_sizes[2] / 8;
    int n4 = N * NF / 4;
    int nb2 = (2 * N + 255) / 256;   // 2 threads per node

    k_pre  <<<(n4 + 255) / 256, 256>>>((const int*)eidx, n4);
    k_edge <<<2048, 256>>>(x, eidx, ea, We, be, E);
    k_gemm1<<<nb2, 256>>>(x, epsp, W1, b1, N);
    k_gemm2<<<nb2, 256>>>(g1, bt1, W2, b2, N);       // profiled (launch idx 3)
    k_out  <<<nb2, 256>>>(g2, bt2, W3, b3, out, N);
}

// round 16
// speedup vs baseline: 1.1487x; 1.1487x over previous
#include <cuda_runtime.h>
#include <math.h>
#include <stdint.h>

// Problem-fixed sizes: N=100000, E=3200000, NF=16, H=32, HO=64
#define NMAX 100000
#define NF 16
#define H  32
#define HO 64
#define NBANK 8

__device__ float  g_agg[NMAX * NF];
__device__ float  g_h1 [NMAX * H];
__device__ float  g_h2 [NMAX * H];
__device__ double g_s1 [NBANK * 64];   // per-bank: sum[32], sumsq[32]
__device__ double g_s2 [NBANK * 64];
__device__ int    g_is64;

__device__ __forceinline__ float gelu_exact(float v) {
    return 0.5f * v * (1.0f + erff(v * 0.70710678118654752f));
}

// Packed dual-FMA (Blackwell FFMA2): two IEEE fp32 FMAs in one instruction.
__device__ __forceinline__ float2 ffma2(float2 a, float2 b, float2 c) {
    unsigned long long au = *reinterpret_cast<unsigned long long*>(&a);
    unsigned long long bu = *reinterpret_cast<unsigned long long*>(&b);
    unsigned long long cu = *reinterpret_cast<unsigned long long*>(&c);
    unsigned long long du;
    asm("fma.rn.f32x2 %0, %1, %2, %3;" : "=l"(du) : "l"(au), "l"(bu), "l"(cu));
    return *reinterpret_cast<float2*>(&du);
}

// ---------------------------------------------------------------------------
// K0: zero g_agg + banked stats; detect edge_index dtype
// ---------------------------------------------------------------------------
__global__ __launch_bounds__(256) void k_pre(const int* __restrict__ eidx32,
                                             int n4) {
    int i = blockIdx.x * blockDim.x + threadIdx.x;
    if (i < n4) ((float4*)g_agg)[i] = make_float4(0.f, 0.f, 0.f, 0.f);
    if (blockIdx.x == 0) {
        #pragma unroll
        for (int k = 0; k < NBANK * 64 / 256; k++) {
            g_s1[threadIdx.x + k * 256] = 0.0;
            g_s2[threadIdx.x + k * 256] = 0.0;
        }
        if (threadIdx.x == 0) {
            int nz = 0;
            #pragma unroll
            for (int k = 0; k < 64; k++) nz |= eidx32[2 * k + 1];
            g_is64 = (nz == 0) ? 1 : 0;
        }
    }
}

// ---------------------------------------------------------------------------
// K1: edge kernel (R9 structure, FFMA2 message math): 4 threads/edge,
// grid-stride, index prefetch, weights in registers, __ldcs for idx/ea.
// ---------------------------------------------------------------------------
__global__ __launch_bounds__(256) void k_edge(const float* __restrict__ x,
                                              const void*  __restrict__ eidx,
                                              const float* __restrict__ ea,
                                              const float* __restrict__ We,
                                              const float* __restrict__ be,
                                              int E) {
    int t = blockIdx.x * blockDim.x + threadIdx.x;
    int c = t & 3;

    float2 w2[8][2];
    #pragma unroll
    for (int k = 0; k < 8; k++) {
        float4 wv = __ldg((const float4*)(We + k * 16) + c);
        w2[k][0] = make_float2(wv.x, wv.y);
        w2[k][1] = make_float2(wv.z, wv.w);
    }
    float4 bv = __ldg(((const float4*)be) + c);
    int is64 = g_is64;

    int total  = E * 4;
    int stride = gridDim.x * blockDim.x;
    const int*       p32 = (const int*)eidx;
    const long long* p64 = (const long long*)eidx;

    int gt = t;
    if (gt >= total) return;

    int src, dst;
    {
        int e = gt >> 2;
        if (is64) { src = (int)__ldcs(p64 + e); dst = (int)__ldcs(p64 + e + E); }
        else      { src = __ldcs(p32 + e);      dst = __ldcs(p32 + e + E);      }
    }

    while (gt < total) {
        int gtn = gt + stride;
        int srcN = 0, dstN = 0;
        if (gtn < total) {
            int en = gtn >> 2;
            if (is64) { srcN = (int)__ldcs(p64 + en); dstN = (int)__ldcs(p64 + en + E); }
            else      { srcN = __ldcs(p32 + en);      dstN = __ldcs(p32 + en + E);      }
        }

        int e = gt >> 2;
        float4 xv = __ldg((const float4*)(x + (size_t)src * 16) + c);
        const float4* ear = (const float4*)(ea + (size_t)e * 8);
        float4 a0 = __ldcs(ear);
        float4 a1 = __ldcs(ear + 1);
        float av[8] = {a0.x, a0.y, a0.z, a0.w, a1.x, a1.y, a1.z, a1.w};

        float2 m01 = make_float2(bv.x, bv.y);
        float2 m23 = make_float2(bv.z, bv.w);
        #pragma unroll
        for (int k = 0; k < 8; k++) {
            float2 ak = make_float2(av[k], av[k]);
            m01 = ffma2(ak, w2[k][0], m01);
            m23 = ffma2(ak, w2[k][1], m23);
        }

        float4 r;
        r.x = fmaxf(xv.x + m01.x, 0.0f);
        r.y = fmaxf(xv.y + m01.y, 0.0f);
        r.z = fmaxf(xv.z + m23.x, 0.0f);
        r.w = fmaxf(xv.w + m23.y, 0.0f);
        atomicAdd((float4*)(g_agg + (size_t)dst * 16) + c, r);

        gt = gtn; src = srcN; dst = dstN;
    }
}

// ---------------------------------------------------------------------------
// stats epilogue, acc2[16] (32 features) per thread (1 thr/node kernels)
// ---------------------------------------------------------------------------
__device__ __forceinline__ void stats_epilogue32(const float2* acc2, bool valid,
                                                 double* sums) {
    __shared__ float tr[8][16][33];
    __shared__ float comb[8][32];
    int lane = threadIdx.x & 31;
    int wid  = threadIdx.x >> 5;
    int f    = lane & 15;
    bool isq = lane >= 16;
    int bank = blockIdx.x & (NBANK - 1);

    float red[2];
    #pragma unroll
    for (int half = 0; half < 2; half++) {
        if (half) __syncwarp();
        #pragma unroll
        for (int j2 = 0; j2 < 8; j2++) {
            float2 v = valid ? acc2[half * 8 + j2] : make_float2(0.f, 0.f);
            tr[wid][2 * j2 + 0][lane] = v.x;
            tr[wid][2 * j2 + 1][lane] = v.y;
        }
        __syncwarp();
        float r = 0.0f;
        #pragma unroll
        for (int k = 0; k < 32; k++) {
            float v = tr[wid][f][k];
            r = fmaf(v, isq ? v : 1.0f, r);
        }
        red[half] = r;
    }

    #pragma unroll
    for (int half = 0; half < 2; half++) {
        comb[wid][lane] = red[half];
        __syncthreads();
        if (wid == 0) {
            float ts = 0.0f;
            #pragma unroll
            for (int w = 0; w < 8; w++) ts += comb[w][lane];
            atomicAdd(&sums[bank * 64 + (isq ? 32 : 0) + half * 16 + f],
                      (double)ts);
        }
        __syncthreads();
    }
}

// ---------------------------------------------------------------------------
// stats epilogue, acc2[8] (16 features) per thread (2 thr/node, gemm1):
// lane L holds features [(L&1)*16,+16) of node (L>>1); stride-2 reduce.
// ---------------------------------------------------------------------------
__device__ __forceinline__ void stats_epilogue16(const float2* acc2, bool valid,
                                                 double* sums) {
    __shared__ float tr[8][16][33];
    __shared__ float comb[8][32];
    int lane = threadIdx.x & 31;
    int wid  = threadIdx.x >> 5;
    int f    = lane & 15;
    bool isq = lane >= 16;
    int bank = blockIdx.x & (NBANK - 1);

    #pragma unroll
    for (int j2 = 0; j2 < 8; j2++) {
        float2 v = valid ? acc2[j2] : make_float2(0.f, 0.f);
        tr[wid][2 * j2 + 0][lane] = v.x;
        tr[wid][2 * j2 + 1][lane] = v.y;
    }
    __syncwarp();

    float red[2];
    #pragma unroll
    for (int h = 0; h < 2; h++) {
        float r = 0.0f;
        #pragma unroll
        for (int k = 0; k < 16; k++) {
            float v = tr[wid][f][2 * k + h];
            r = fmaf(v, isq ? v : 1.0f, r);
        }
        red[h] = r;
    }

    #pragma unroll
    for (int h = 0; h < 2; h++) {
        comb[wid][lane] = red[h];
        __syncthreads();
        if (wid == 0) {
            float ts = 0.0f;
            #pragma unroll
            for (int w = 0; w < 8; w++) ts += comb[w][lane];
            atomicAdd(&sums[bank * 64 + (isq ? 32 : 0) + h * 16 + f],
                      (double)ts);
        }
        __syncthreads();
    }
}

// ---------------------------------------------------------------------------
// BN finalize inline: sum the 8 banks, then scale/shift
// ---------------------------------------------------------------------------
__device__ __forceinline__ void fin_inline(const double* __restrict__ sums,
                                           const float* __restrict__ gamma,
                                           const float* __restrict__ beta,
                                           int N, float* ssc, float* ssh) {
    if (threadIdx.x < H) {
        int f = threadIdx.x;
        double s = 0.0, q = 0.0;
        #pragma unroll
        for (int b = 0; b < NBANK; b++) {
            s += sums[b * 64 + f];
            q += sums[b * 64 + 32 + f];
        }
        double mean = s / (double)N;
        double var  = q / (double)N - mean * mean;
        double inv  = 1.0 / sqrt(var + 1e-5);
        ssc[f] = (float)((double)gamma[f] * inv);
        ssh[f] = (float)((double)beta[f] - mean * (double)gamma[f] * inv);
    }
}

// ---------------------------------------------------------------------------
// K2: h1 = ((1+eps)*x + agg) @ W1 + b1.  R12 form, FFMA2 (2 thr/node).
// ---------------------------------------------------------------------------
__global__ __launch_bounds__(256) void k_gemm1(const float* __restrict__ x,
                                               const float* __restrict__ epsp,
                                               const float* __restrict__ W1,
                                               const float* __restrict__ b1,
                                               int N) {
    __shared__ float sW[NF * H];
    __shared__ float sb[H];
    for (int i = threadIdx.x; i < NF * H; i += blockDim.x) sW[i] = W1[i];
    if (threadIdx.x < H) sb[threadIdx.x] = b1[threadIdx.x];
    __syncthreads();

    int t = blockIdx.x * blockDim.x + threadIdx.x;
    int n = t >> 1, half = t & 1;
    bool valid = n < N;
    int nc = valid ? n : 0;
    float sc = 1.0f + epsp[0];

    const float4* ar = (const float4*)(g_agg + (size_t)nc * NF);
    const float4* xr = (const float4*)(x     + (size_t)nc * NF);
    int hoff = half * 16;

    float2 acc2[8];
    #pragma unroll
    for (int j2 = 0; j2 < 8; j2++)
        acc2[j2] = make_float2(sb[hoff + 2*j2], sb[hoff + 2*j2 + 1]);

    #pragma unroll 1
    for (int cph = 0; cph < 4; cph++) {
        float4 v  = ar[cph];
        float4 xv = xr[cph];
        float2 a0 = make_float2(fmaf(sc, xv.x, v.x), fmaf(sc, xv.x, v.x));
        float2 a1 = make_float2(fmaf(sc, xv.y, v.y), fmaf(sc, xv.y, v.y));
        float2 a2 = make_float2(fmaf(sc, xv.z, v.z), fmaf(sc, xv.z, v.z));
        float2 a3 = make_float2(fmaf(sc, xv.w, v.w), fmaf(sc, xv.w, v.w));
        const float4* w0 = (const float4*)(sW + (4 * cph + 0) * H + hoff);
        const float4* w1 = (const float4*)(sW + (4 * cph + 1) * H + hoff);
        const float4* w2 = (const float4*)(sW + (4 * cph + 2) * H + hoff);
        const float4* w3 = (const float4*)(sW + (4 * cph + 3) * H + hoff);
        #pragma unroll
        for (int j4 = 0; j4 < 4; j4++) {
            float4 wa = w0[j4];
            acc2[2*j4]   = ffma2(a0, make_float2(wa.x, wa.y), acc2[2*j4]);
            acc2[2*j4+1] = ffma2(a0, make_float2(wa.z, wa.w), acc2[2*j4+1]);
            float4 wb = w1[j4];
            acc2[2*j4]   = ffma2(a1, make_float2(wb.x, wb.y), acc2[2*j4]);
            acc2[2*j4+1] = ffma2(a1, make_float2(wb.z, wb.w), acc2[2*j4+1]);
            float4 wc = w2[j4];
            acc2[2*j4]   = ffma2(a2, make_float2(wc.x, wc.y), acc2[2*j4]);
            acc2[2*j4+1] = ffma2(a2, make_float2(wc.z, wc.w), acc2[2*j4+1]);
            float4 wd = w3[j4];
            acc2[2*j4]   = ffma2(a3, make_float2(wd.x, wd.y), acc2[2*j4]);
            acc2[2*j4+1] = ffma2(a3, make_float2(wd.z, wd.w), acc2[2*j4+1]);
        }
    }

    if (valid) {
        float4* hr = (float4*)(g_h1 + (size_t)n * H + hoff);
        #pragma unroll
        for (int cph = 0; cph < 4; cph++)
            hr[cph] = make_float4(acc2[2*cph].x, acc2[2*cph].y,
                                  acc2[2*cph+1].x, acc2[2*cph+1].y);
    }
    stats_epilogue16(acc2, valid, g_s1);
}

// ---------------------------------------------------------------------------
// K3: h2 = gelu(bn1(h1)) @ W2 + b2.  R14 form, FFMA2 (1 thr/node, streamed).
// ---------------------------------------------------------------------------
__global__ __launch_bounds__(256) void k_gemm2(const float* __restrict__ g1,
                                               const float* __restrict__ bt1,
                                               const float* __restrict__ W2,
                                               const float* __restrict__ b2,
                                               int N) {
    __shared__ float sW[H * H];
    __shared__ float sb[H], ssc[H], ssh[H];
    for (int i = threadIdx.x; i < H * H; i += blockDim.x) sW[i] = W2[i];
    if (threadIdx.x < H) sb[threadIdx.x] = b2[threadIdx.x];
    fin_inline(g_s1, g1, bt1, N, ssc, ssh);
    __syncthreads();

    int n = blockIdx.x * blockDim.x + threadIdx.x;
    bool valid = n < N;
    int nc = valid ? n : 0;
    const float4* hr = (const float4*)(g_h1 + (size_t)nc * H);

    float2 acc2[16];
    #pragma unroll
    for (int j2 = 0; j2 < 16; j2++)
        acc2[j2] = make_float2(sb[2*j2], sb[2*j2 + 1]);

    #pragma unroll 1
    for (int cph = 0; cph < 8; cph++) {
        float4 v = hr[cph];
        float s0 = gelu_exact(fmaf(v.x, ssc[4*cph+0], ssh[4*cph+0]));
        float s1 = gelu_exact(fmaf(v.y, ssc[4*cph+1], ssh[4*cph+1]));
        float s2 = gelu_exact(fmaf(v.z, ssc[4*cph+2], ssh[4*cph+2]));
        float s3 = gelu_exact(fmaf(v.w, ssc[4*cph+3], ssh[4*cph+3]));
        float2 y0 = make_float2(s0, s0);
        float2 y1 = make_float2(s1, s1);
        float2 y2 = make_float2(s2, s2);
        float2 y3 = make_float2(s3, s3);
        const float4* w0 = (const float4*)(sW + (4 * cph + 0) * H);
        const float4* w1 = (const float4*)(sW + (4 * cph + 1) * H);
        const float4* w2 = (const float4*)(sW + (4 * cph + 2) * H);
        const float4* w3 = (const float4*)(sW + (4 * cph + 3) * H);
        #pragma unroll
        for (int j4 = 0; j4 < 8; j4++) {
            float4 wa = w0[j4];
            acc2[2*j4]   = ffma2(y0, make_float2(wa.x, wa.y), acc2[2*j4]);
            acc2[2*j4+1] = ffma2(y0, make_float2(wa.z, wa.w), acc2[2*j4+1]);
            float4 wb = w1[j4];
            acc2[2*j4]   = ffma2(y1, make_float2(wb.x, wb.y), acc2[2*j4]);
            acc2[2*j4+1] = ffma2(y1, make_float2(wb.z, wb.w), acc2[2*j4+1]);
            float4 wc = w2[j4];
            acc2[2*j4]   = ffma2(y2, make_float2(wc.x, wc.y), acc2[2*j4]);
            acc2[2*j4+1] = ffma2(y2, make_float2(wc.z, wc.w), acc2[2*j4+1]);
            float4 wd = w3[j4];
            acc2[2*j4]   = ffma2(y3, make_float2(wd.x, wd.y), acc2[2*j4]);
            acc2[2*j4+1] = ffma2(y3, make_float2(wd.z, wd.w), acc2[2*j4+1]);
        }
    }

    if (valid) {
        float4* o = (float4*)(g_h2 + (size_t)n * H);
        #pragma unroll
        for (int cph = 0; cph < 8; cph++)
            o[cph] = make_float4(acc2[2*cph].x, acc2[2*cph].y,
                                 acc2[2*cph+1].x, acc2[2*cph+1].y);
    }
    stats_epilogue32(acc2, valid, g_s2);
}

// ---------------------------------------------------------------------------
// K4: out = gelu(bn2(h2)) @ W3 + b3.  R14 form, FFMA2: y[32] once,
// 2 passes of acc2[16] (32 outputs each).
// ---------------------------------------------------------------------------
__global__ __launch_bounds__(256) void k_out(const float* __restrict__ g2,
                                             const float* __restrict__ bt2,
                                             const float* __restrict__ W3,
                                             const float* __restrict__ b3,
                                             float* __restrict__ out,
                                             int N) {
    __shared__ float sW[H * HO];
    __shared__ float sb[HO], ssc[H], ssh[H];
    for (int i = threadIdx.x; i < H * HO; i += blockDim.x) sW[i] = W3[i];
    if (threadIdx.x < HO) sb[threadIdx.x] = b3[threadIdx.x];
    fin_inline(g_s2, g2, bt2, N, ssc, ssh);
    __syncthreads();

    int n = blockIdx.x * blockDim.x + threadIdx.x;
    if (n >= N) return;
    const float4* hr = (const float4*)(g_h2 + (size_t)n * H);
    float4* orow = (float4*)(out + (size_t)n * HO);

    float y[H];
    #pragma unroll
    for (int cph = 0; cph < 8; cph++) {
        float4 v = hr[cph];
        y[4*cph+0] = gelu_exact(fmaf(v.x, ssc[4*cph+0], ssh[4*cph+0]));
        y[4*cph+1] = gelu_exact(fmaf(v.y, ssc[4*cph+1], ssh[4*cph+1]));
        y[4*cph+2] = gelu_exact(fmaf(v.z, ssc[4*cph+2], ssh[4*cph+2]));
        y[4*cph+3] = gelu_exact(fmaf(v.w, ssc[4*cph+3], ssh[4*cph+3]));
    }

    #pragma unroll 1
    for (int jb = 0; jb < 2; jb++) {
        float2 acc2[16];
        #pragma unroll
        for (int j2 = 0; j2 < 16; j2++)
            acc2[j2] = make_float2(sb[jb*32 + 2*j2], sb[jb*32 + 2*j2 + 1]);

        #pragma unroll
        for (int k = 0; k < H; k++) {
            float2 yk = make_float2(y[k], y[k]);
            const float4* wr = (const float4*)(sW + k * HO + jb * 32);
            #pragma unroll
            for (int j4 = 0; j4 < 8; j4++) {
                float4 wa = wr[j4];
                acc2[2*j4]   = ffma2(yk, make_float2(wa.x, wa.y), acc2[2*j4]);
                acc2[2*j4+1] = ffma2(yk, make_float2(wa.z, wa.w), acc2[2*j4+1]);
            }
        }
        #pragma unroll
        for (int cph = 0; cph < 8; cph++)
            orow[jb * 8 + cph] = make_float4(acc2[2*cph].x, acc2[2*cph].y,
                                             acc2[2*cph+1].x, acc2[2*cph+1].y);
    }
}

// ---------------------------------------------------------------------------
extern "C" void kernel_launch(void* const* d_in, const int* in_sizes, int n_in,
                              void* d_out, int out_size) {
    const float* x    = (const float*)d_in[0];
    const void*  eidx =               d_in[1];
    const float* ea   = (const float*)d_in[2];
    const float* We   = (const float*)d_in[3];
    const float* be   = (const float*)d_in[4];
    const float* W1   = (const float*)d_in[5];
    const float* b1   = (const float*)d_in[6];
    const float* g1   = (const float*)d_in[7];
    const float* bt1  = (const float*)d_in[8];
    const float* W2   = (const float*)d_in[9];
    const float* b2   = (const float*)d_in[10];
    const float* epsp = (const float*)d_in[11];
    const float* g2   = (const float*)d_in[12];
    const float* bt2  = (const float*)d_in[13];
    const float* W3   = (const float*)d_in[14];
    const float* b3   = (const float*)d_in[15];
    float* out = (float*)d_out;

    int N = in_sizes[0] / NF;
    int E = in_sizes[2] / 8;
    int n4 = N * NF / 4;
    int nb  = (N + 255) / 256;       // 1 thread per node
    int nb2 = (2 * N + 255) / 256;   // 2 threads per node (gemm1)

    k_pre  <<<(n4 + 255) / 256, 256>>>((const int*)eidx, n4);
    k_edge <<<2048, 256>>>(x, eidx, ea, We, be, E);
    k_gemm1<<<nb2, 256>>>(x, epsp, W1, b1, N);
    k_gemm2<<<nb,  256>>>(g1, bt1, W2, b2, N);       // profiled (launch idx 3)
    k_out  <<<nb,  256>>>(g2, bt2, W3, b3, out, N);
}